// round 1
// baseline (speedup 1.0000x reference)
#include <cuda_runtime.h>
#include <math_constants.h>
#include <cstdint>

// Problem constants
#define Bc 2
#define Sc 1024
#define Dc 512
#define Hc 8
#define Fc 3072
#define Kt 64
#define BS (Bc*Sc)   // 2048

// ---------------- scratch (static device globals; no allocations) ----------------
__device__ __align__(16) float g_act  [BS*Dc];                       // 1.05M
__device__ __align__(16) float g_invln[BS];
__device__ __align__(16) float g_ctx  [(size_t)Bc*Hc*Sc*Dc];         // 8.4M
__device__ __align__(16) float g_z    [BS*Dc];
__device__ __align__(16) float g_EW   [(size_t)Hc*Fc*Dc];            // 12.6M
__device__ __align__(16) float g_approx[(size_t)BS*Fc];              // 6.3M
__device__ __align__(16) float g_vw   [(size_t)Hc*Fc*Fc];            // 75.5M
__device__ __align__(16) float g_Abuf [(size_t)Bc*Hc*Sc*Fc];         // 50.3M
__device__ __align__(16) float g_up   [(size_t)BS*Fc];               // 6.3M
__device__ __align__(16) float g_v    [Dc];
__device__ __align__(16) float g_ev   [Fc];
__device__ __align__(16) float g_bias0[Fc];
__device__ __align__(16) float g_decT [(size_t)Fc*Dc];               // 1.6M

// ---------------- generic tiled fp32 GEMM: C[M,N] (+)= sum_h A_h[M,K] * B_h ----------------
// TRANSB=false: B is [K,N] row-major (ldb = N). TRANSB=true: B is [N,K] row-major (ldb = K).
// EPI: 0 none, 1 multiply by mask[M,N], 2 add bias[n] + vec[n]*scale[m]. ACCUM: C += result.
// Requires M%128==0, N%128==0, K%16==0.
template<bool TRANSB, int EPI, bool ACCUM>
__global__ __launch_bounds__(256, 2)
void gemm_k(const float* __restrict__ A, const float* __restrict__ B,
            float* __restrict__ C,
            int M, int N, int K, int nH,
            long sAh, long sBh, long sAz, long sBz, int zdivB, long sCz,
            const float* __restrict__ e_mask,
            const float* __restrict__ e_bias,
            const float* __restrict__ e_vec,
            const float* __restrict__ e_scale)
{
    __shared__ float As[16][128];
    __shared__ float Bs[16][128];
    const int tid = threadIdx.x;
    const int tx = tid & 15, ty = tid >> 4;
    const int bm = blockIdx.y * 128;
    const int bn = blockIdx.x * 128;
    const int z  = blockIdx.z;
    const float* Ab = A + (long)z * sAz;
    const float* Bb = B + (long)(z / zdivB) * sBz;
    float*       Cb = C + (long)z * sCz;

    float acc[8][8];
    #pragma unroll
    for (int i = 0; i < 8; ++i)
        #pragma unroll
        for (int j = 0; j < 8; ++j) acc[i][j] = 0.f;

    for (int h = 0; h < nH; ++h) {
        const float* Ah = Ab + (long)h * sAh;
        const float* Bh = Bb + (long)h * sBh;
        for (int k0 = 0; k0 < K; k0 += 16) {
            // load A tile (transposed into smem): rows bm..bm+127, cols k0..k0+15
            #pragma unroll
            for (int i = 0; i < 2; ++i) {
                int li = tid + i * 256;
                int row = li >> 2, c4 = (li & 3) << 2;
                const float4 va = *reinterpret_cast<const float4*>(
                    Ah + (long)(bm + row) * K + (k0 + c4));
                As[c4 + 0][row] = va.x; As[c4 + 1][row] = va.y;
                As[c4 + 2][row] = va.z; As[c4 + 3][row] = va.w;
            }
            if (TRANSB) {
                #pragma unroll
                for (int i = 0; i < 2; ++i) {
                    int li = tid + i * 256;
                    int row = li >> 2, c4 = (li & 3) << 2;
                    const float4 vb = *reinterpret_cast<const float4*>(
                        Bh + (long)(bn + row) * K + (k0 + c4));
                    Bs[c4 + 0][row] = vb.x; Bs[c4 + 1][row] = vb.y;
                    Bs[c4 + 2][row] = vb.z; Bs[c4 + 3][row] = vb.w;
                }
            } else {
                #pragma unroll
                for (int i = 0; i < 2; ++i) {
                    int li = tid + i * 256;
                    int row = li >> 5, c = (li & 31) << 2;
                    *reinterpret_cast<float4*>(&Bs[row][c]) =
                        *reinterpret_cast<const float4*>(
                            Bh + (long)(k0 + row) * N + (bn + c));
                }
            }
            __syncthreads();
            #pragma unroll
            for (int k = 0; k < 16; ++k) {
                float a[8], b[8];
                *reinterpret_cast<float4*>(&a[0]) = *reinterpret_cast<const float4*>(&As[k][ty * 8]);
                *reinterpret_cast<float4*>(&a[4]) = *reinterpret_cast<const float4*>(&As[k][ty * 8 + 4]);
                *reinterpret_cast<float4*>(&b[0]) = *reinterpret_cast<const float4*>(&Bs[k][tx * 8]);
                *reinterpret_cast<float4*>(&b[4]) = *reinterpret_cast<const float4*>(&Bs[k][tx * 8 + 4]);
                #pragma unroll
                for (int i = 0; i < 8; ++i)
                    #pragma unroll
                    for (int j = 0; j < 8; ++j)
                        acc[i][j] = fmaf(a[i], b[j], acc[i][j]);
            }
            __syncthreads();
        }
    }
    // epilogue
    #pragma unroll
    for (int i = 0; i < 8; ++i) {
        const long r = bm + ty * 8 + i;
        #pragma unroll
        for (int j = 0; j < 8; ++j) {
            const long c = bn + tx * 8 + j;
            float vv = acc[i][j];
            if (EPI == 1) vv *= e_mask[r * N + c];
            if (EPI == 2) vv += e_bias[c] + e_vec[c] * e_scale[r];
            if (ACCUM)    vv += Cb[r * N + c];
            Cb[r * N + c] = vv;
        }
    }
}

// ---------------- small kernels ----------------
__global__ void prep_kernel(const float* __restrict__ resid, const float* __restrict__ ln,
                            float* __restrict__ act, float* __restrict__ invln)
{
    int idx = blockIdx.x * 256 + threadIdx.x;
    if (idx >= BS * Dc) return;
    int m = idx >> 9;  // /Dc
    float il = 1.f / ln[m];
    act[idx] = resid[idx] * il;
    if ((idx & (Dc - 1)) == 0) invln[m] = il;
}

__global__ void uppost_kernel(const float* __restrict__ pf, const float* __restrict__ invln,
                              float* __restrict__ up)
{
    long idx = (long)blockIdx.x * 256 + threadIdx.x;
    if (idx >= (long)BS * Fc) return;
    int m = (int)(idx / Fc);
    up[idx] = pf[idx] * invln[m];
}

// v[o] = sum_{h,i} W_OV[h,i,o] * (ub1[i]+ub2[i])
__global__ void vec1_kernel(const float* __restrict__ W_OV,
                            const float* __restrict__ ub1, const float* __restrict__ ub2,
                            float* __restrict__ v)
{
    int o = blockIdx.x * 256 + threadIdx.x;
    if (o >= Dc) return;
    float acc = 0.f;
    for (int h = 0; h < Hc; ++h)
        for (int i = 0; i < Dc; ++i)
            acc += W_OV[((long)h * Dc + i) * Dc + o] * (ub1[i] + ub2[i]);
    v[o] = acc;
}

// ev[d] = enc_w[d,:]@v ; bias0[d] = enc_w[d,:]@b_O + enc_b[d] - enc_w[d,:]@b_dec
__global__ void vec2_kernel(const float* __restrict__ enc_w, const float* __restrict__ v,
                            const float* __restrict__ b_O, const float* __restrict__ b_dec,
                            const float* __restrict__ enc_b,
                            float* __restrict__ ev, float* __restrict__ bias0)
{
    int d = blockIdx.x * 256 + threadIdx.x;
    if (d >= Fc) return;
    float e = 0.f, bo = 0.f, bd = 0.f;
    for (int o = 0; o < Dc; ++o) {
        float w = enc_w[(long)d * Dc + o];
        e += w * v[o]; bo += w * b_O[o]; bd += w * b_dec[o];
    }
    ev[d] = e;
    bias0[d] = bo + enc_b[d] - bd;
}

// dec_w [D,F] -> decT [F,D]
__global__ void transpose_kernel(const float* __restrict__ dec_w, float* __restrict__ decT)
{
    __shared__ float tile[32][33];
    int bx = blockIdx.x * 32, by = blockIdx.y * 32;  // bx over F, by over D
    tile[threadIdx.y][threadIdx.x] = dec_w[(long)(by + threadIdx.y) * Fc + bx + threadIdx.x];
    __syncthreads();
    decT[(long)(bx + threadIdx.y) * Dc + by + threadIdx.x] = tile[threadIdx.x][threadIdx.y];
}

// per-row top-64 + relu + scatter + sparse decode
__global__ void topk_kernel(const float* __restrict__ approx,
                            const float* __restrict__ decT,
                            const float* __restrict__ b_dec,
                            float* __restrict__ out)
{
    const int m = blockIdx.x;  // 0..2047
    const float* row = approx + (long)m * Fc;
    float* feat  = out + (long)m * Fc;
    float* recon = out + (long)BS * Fc + (long)m * Dc;

    __shared__ float sv[Fc];
    __shared__ float rv[256];
    __shared__ int   ri[256];
    __shared__ int   s_idx[Kt];
    __shared__ float s_val[Kt];

    const int t = threadIdx.x;
    for (int u = t; u < Fc; u += 256) { sv[u] = row[u]; feat[u] = 0.f; }
    __syncthreads();

    for (int it = 0; it < Kt; ++it) {
        float bv = -CUDART_INF_F; int bi = 0x7fffffff;
        for (int u = t; u < Fc; u += 256) {
            float v = sv[u];
            if (v > bv) { bv = v; bi = u; }
        }
        rv[t] = bv; ri[t] = bi;
        __syncthreads();
        for (int s = 128; s > 0; s >>= 1) {
            if (t < s) {
                float v2 = rv[t + s]; int i2 = ri[t + s];
                if (v2 > rv[t] || (v2 == rv[t] && i2 < ri[t])) { rv[t] = v2; ri[t] = i2; }
            }
            __syncthreads();
        }
        if (t == 0) {
            s_idx[it] = ri[0];
            s_val[it] = fmaxf(rv[0], 0.f);  // relu
            sv[ri[0]] = -CUDART_INF_F;
        }
        __syncthreads();
    }
    if (t < Kt) feat[s_idx[t]] = s_val[t];
    for (int o = t; o < Dc; o += 256) {
        float r = b_dec[o];
        #pragma unroll 8
        for (int j = 0; j < Kt; ++j)
            r = fmaf(s_val[j], decT[(long)s_idx[j] * Dc + o], r);
        recon[o] = r;
    }
}

// ---------------- launch ----------------
extern "C" void kernel_launch(void* const* d_in, const int* in_sizes, int n_in,
                              void* d_out, int out_size)
{
    const float* resid    = (const float*)d_in[0];
    const float* ln       = (const float*)d_in[1];
    const float* probs    = (const float*)d_in[2];
    const float* W_OV     = (const float*)d_in[3];
    const float* b_O      = (const float*)d_in[4];
    const float* enc_w    = (const float*)d_in[5];
    const float* enc_b    = (const float*)d_in[6];
    const float* b_dec    = (const float*)d_in[7];
    const float* dec_w    = (const float*)d_in[8];
    const float* up1_dec  = (const float*)d_in[9];
    const float* up1_bdec = (const float*)d_in[10];
    const float* pf1      = (const float*)d_in[11];
    const float* mask1    = (const float*)d_in[12];
    const float* up2_dec  = (const float*)d_in[13];
    const float* up2_bdec = (const float*)d_in[14];
    const float* pf2      = (const float*)d_in[15];
    const float* mask2    = (const float*)d_in[16];
    float* out = (float*)d_out;

    float *act, *invln, *ctx, *zb, *EW, *approx, *vw, *Abuf, *up, *vv, *ev, *bias0, *decT;
    cudaGetSymbolAddress((void**)&act,   g_act);
    cudaGetSymbolAddress((void**)&invln, g_invln);
    cudaGetSymbolAddress((void**)&ctx,   g_ctx);
    cudaGetSymbolAddress((void**)&zb,    g_z);
    cudaGetSymbolAddress((void**)&EW,    g_EW);
    cudaGetSymbolAddress((void**)&approx,g_approx);
    cudaGetSymbolAddress((void**)&vw,    g_vw);
    cudaGetSymbolAddress((void**)&Abuf,  g_Abuf);
    cudaGetSymbolAddress((void**)&up,    g_up);
    cudaGetSymbolAddress((void**)&vv,    g_v);
    cudaGetSymbolAddress((void**)&ev,    g_ev);
    cudaGetSymbolAddress((void**)&bias0, g_bias0);
    cudaGetSymbolAddress((void**)&decT,  g_decT);

    // prep: act = resid/ln, invln
    prep_kernel<<<(BS * Dc + 255) / 256, 256>>>(resid, ln, act, invln);
    // bias vectors
    vec1_kernel<<<2, 256>>>(W_OV, up1_bdec, up2_bdec, vv);
    vec2_kernel<<<Fc / 256, 256>>>(enc_w, vv, b_O, b_dec, enc_b, ev, bias0);
    // decoder transpose
    transpose_kernel<<<dim3(Fc / 32, Dc / 32), dim3(32, 32)>>>(dec_w, decT);

    // K1: ctx[b,h] = probs[b,h] @ act[b]          (NN, z = b*8+h)
    gemm_k<false, 0, false><<<dim3(Dc / 128, Sc / 128, Bc * Hc), 256>>>(
        probs, act, ctx, Sc, Dc, Sc, 1,
        0, 0, (long)Sc * Sc, (long)Sc * Dc, Hc, (long)Sc * Dc,
        nullptr, nullptr, nullptr, nullptr);

    // K2: z[b] = sum_h ctx[b,h] @ W_OV[h]          (NN, nH=8, z = b)
    gemm_k<false, 0, false><<<dim3(Dc / 128, Sc / 128, Bc), 256>>>(
        ctx, W_OV, zb, Sc, Dc, Dc, Hc,
        (long)Sc * Dc, (long)Dc * Dc, (long)Hc * Sc * Dc, 0, 1, (long)Sc * Dc,
        nullptr, nullptr, nullptr, nullptr);

    // EW[h] = enc_w @ W_OV[h]^T                    (NT, z = h)
    gemm_k<true, 0, false><<<dim3(Dc / 128, Fc / 128, Hc), 256>>>(
        enc_w, W_OV, EW, Fc, Dc, Dc, 1,
        0, 0, 0, (long)Dc * Dc, 1, (long)Fc * Dc,
        nullptr, nullptr, nullptr, nullptr);

    // K3: approx = zb @ enc_w^T + bias0[d] + ev[d]*invln[m]   (NT, EPI2)
    gemm_k<true, 2, false><<<dim3(Fc / 128, BS / 128, 1), 256>>>(
        zb, enc_w, approx, BS, Fc, Dc, 1,
        0, 0, 0, 0, 1, 0,
        nullptr, bias0, ev, invln);

    const float* updecs[2] = {up1_dec, up2_dec};
    const float* pfs[2]    = {pf1, pf2};
    const float* masks[2]  = {mask1, mask2};
    for (int j = 0; j < 2; ++j) {
        // up_post = pf / ln
        uppost_kernel<<<(int)(((long)BS * Fc + 255) / 256), 256>>>(pfs[j], invln, up);

        // K4c: vw[h] = (EW[h] @ up_dec) * mask     (NN, z = h, EPI1)
        gemm_k<false, 1, false><<<dim3(Fc / 128, Fc / 128, Hc), 256>>>(
            EW, updecs[j], vw, Fc, Fc, Dc, 1,
            0, 0, (long)Fc * Dc, 0, 1, (long)Fc * Fc,
            masks[j], nullptr, nullptr, nullptr);

        // K5: Abuf[b,h] = probs[b,h] @ up_post[b]  (NN, z = b*8+h)
        gemm_k<false, 0, false><<<dim3(Fc / 128, Sc / 128, Bc * Hc), 256>>>(
            probs, up, Abuf, Sc, Fc, Sc, 1,
            0, 0, (long)Sc * Sc, (long)Sc * Fc, Hc, (long)Sc * Fc,
            nullptr, nullptr, nullptr, nullptr);

        // K6: approx[b] += sum_h Abuf[b,h] @ vw[h]^T   (NT, nH=8, ACCUM, z = b)
        gemm_k<true, 0, true><<<dim3(Fc / 128, Sc / 128, Bc), 256>>>(
            Abuf, vw, approx, Sc, Fc, Fc, Hc,
            (long)Sc * Fc, (long)Fc * Fc, (long)Hc * Sc * Fc, 0, 1, (long)Sc * Fc,
            nullptr, nullptr, nullptr, nullptr);
    }

    // top-k + relu + scatter + sparse decode
    topk_kernel<<<BS, 256>>>(approx, decT, b_dec, out);
}